// round 2
// baseline (speedup 1.0000x reference)
#include <cuda_runtime.h>

// Problem geometry (fixed by the reference: N=16, C=4, H=W=768)
#define NB 16
#define NC 4
#define MPIX (768 * 768)        // 589824 pixels per image
#define MV   (MPIX / 4)         // 147456 float4 groups per plane
#define BLOCKS_PER_N 72
#define THREADS 256
#define ITERS 8                 // MV / (BLOCKS_PER_N*THREADS) == 8 exactly

// Global scratch for the 64 (n,c) accumulators. No cudaMalloc allowed.
__device__ float g_num[NB * NC];
__device__ float g_den[NB * NC];

__global__ void dice_zero_kernel() {
    int i = threadIdx.x;
    if (i < NB * NC) {
        g_num[i] = 0.0f;
        g_den[i] = 0.0f;
    }
}

__global__ __launch_bounds__(THREADS) void dice_main_kernel(
    const float* __restrict__ predict,
    const int*   __restrict__ target,
    const int*   __restrict__ masks)
{
    const int n     = blockIdx.x / BLOCKS_PER_N;
    const int chunk = blockIdx.x % BLOCKS_PER_N;

    const float4* __restrict__ p  = (const float4*)(predict + (size_t)n * NC * MPIX);
    const int4*   __restrict__ tg = (const int4*)(target + (size_t)n * MPIX);
    const int4*   __restrict__ mk = (const int4*)(masks  + (size_t)n * MPIX);

    float num0 = 0.f, num1 = 0.f, num2 = 0.f, num3 = 0.f;
    float den0 = 0.f, den1 = 0.f, den2 = 0.f, den3 = 0.f;

    const int base   = chunk * THREADS + threadIdx.x;
    const int stride = BLOCKS_PER_N * THREADS;

    #pragma unroll
    for (int it = 0; it < ITERS; it++) {
        const int i = base + it * stride;
        // 6 independent 128B loads -> high MLP
        float4 a = p[i];            // class 0, pixels 4i..4i+3
        float4 b = p[i + MV];       // class 1
        float4 c = p[i + 2 * MV];   // class 2
        float4 d = p[i + 3 * MV];   // class 3
        int4   t = tg[i];
        int4   m = mk[i];

        const float xa[4] = {a.x, a.y, a.z, a.w};
        const float xb[4] = {b.x, b.y, b.z, b.w};
        const float xc[4] = {c.x, c.y, c.z, c.w};
        const float xd[4] = {d.x, d.y, d.z, d.w};
        const int   tt[4] = {t.x, t.y, t.z, t.w};
        const int   mm[4] = {m.x, m.y, m.z, m.w};

        #pragma unroll
        for (int j = 0; j < 4; j++) {
            const float v0 = xa[j], v1 = xb[j], v2 = xc[j], v3 = xd[j];
            const int   tj = tt[j];
            const bool  on = (mm[j] >= 1);

            // 4-way softmax
            float mx = fmaxf(fmaxf(v0, v1), fmaxf(v2, v3));
            float e0 = __expf(v0 - mx);
            float e1 = __expf(v1 - mx);
            float e2 = __expf(v2 - mx);
            float e3 = __expf(v3 - mx);
            float inv = __fdividef(1.0f, e0 + e1 + e2 + e3);

            // one-hot selects (branch-free)
            float h0 = (tj == 0) ? 1.0f : 0.0f;
            float h1 = (tj == 1) ? 1.0f : 0.0f;
            float h2 = (tj == 2) ? 1.0f : 0.0f;
            float h3 = (tj == 3) ? 1.0f : 0.0f;

            // p_eff = mask ? softmax : onehot
            float p0v = on ? e0 * inv : h0;
            float p1v = on ? e1 * inv : h1;
            float p2v = on ? e2 * inv : h2;
            float p3v = on ? e3 * inv : h3;

            // num_c += onehot_c * p_c ; den_c += p_c^2 + onehot_c
            num0 += h0 * p0v;  den0 += p0v * p0v + h0;
            num1 += h1 * p1v;  den1 += p1v * p1v + h1;
            num2 += h2 * p2v;  den2 += p2v * p2v + h2;
            num3 += h3 * p3v;  den3 += p3v * p3v + h3;
        }
    }

    // ---- warp-level reduction (8 values) ----
    #pragma unroll
    for (int off = 16; off > 0; off >>= 1) {
        num0 += __shfl_xor_sync(0xffffffffu, num0, off);
        num1 += __shfl_xor_sync(0xffffffffu, num1, off);
        num2 += __shfl_xor_sync(0xffffffffu, num2, off);
        num3 += __shfl_xor_sync(0xffffffffu, num3, off);
        den0 += __shfl_xor_sync(0xffffffffu, den0, off);
        den1 += __shfl_xor_sync(0xffffffffu, den1, off);
        den2 += __shfl_xor_sync(0xffffffffu, den2, off);
        den3 += __shfl_xor_sync(0xffffffffu, den3, off);
    }

    __shared__ float s_acc[8];
    if (threadIdx.x < 8) s_acc[threadIdx.x] = 0.0f;
    __syncthreads();

    if ((threadIdx.x & 31) == 0) {
        atomicAdd(&s_acc[0], num0);
        atomicAdd(&s_acc[1], num1);
        atomicAdd(&s_acc[2], num2);
        atomicAdd(&s_acc[3], num3);
        atomicAdd(&s_acc[4], den0);
        atomicAdd(&s_acc[5], den1);
        atomicAdd(&s_acc[6], den2);
        atomicAdd(&s_acc[7], den3);
    }
    __syncthreads();

    if (threadIdx.x < 4) {
        atomicAdd(&g_num[n * NC + threadIdx.x], s_acc[threadIdx.x]);
        atomicAdd(&g_den[n * NC + threadIdx.x], s_acc[4 + threadIdx.x]);
    }
}

__global__ void dice_finalize_kernel(float* __restrict__ out) {
    // 64 threads: one (n,c) cell each, then tree-reduce.
    __shared__ float s_loss[64];
    const int i = threadIdx.x;
    float v = 1.0f - (g_num[i] + 1.0f) / (g_den[i] + 1.0f);
    s_loss[i] = v;
    __syncthreads();
    if (i < 32) {
        float x = s_loss[i] + s_loss[i + 32];
        #pragma unroll
        for (int off = 16; off > 0; off >>= 1)
            x += __shfl_xor_sync(0xffffffffu, x, off);
        if (i == 0) out[0] = x * (1.0f / (NB * NC));
    }
}

extern "C" void kernel_launch(void* const* d_in, const int* in_sizes, int n_in,
                              void* d_out, int out_size) {
    const float* predict = (const float*)d_in[0];
    const int*   target  = (const int*)d_in[1];
    const int*   masks   = (const int*)d_in[2];
    float*       out     = (float*)d_out;

    dice_zero_kernel<<<1, 64>>>();
    dice_main_kernel<<<NB * BLOCKS_PER_N, THREADS>>>(predict, target, masks);
    dice_finalize_kernel<<<1, 64>>>(out);
}

// round 3
// speedup vs baseline: 1.0022x; 1.0022x over previous
#include <cuda_runtime.h>

// Problem geometry (fixed by the reference: N=16, C=4, H=W=768)
#define NB 16
#define NC 4
#define MPIX (768 * 768)        // 589824 pixels per image
#define MV   (MPIX / 4)         // 147456 float4 groups per plane
#define BLOCKS_PER_N 72
#define THREADS 256
#define ITERS 8                 // MV / (BLOCKS_PER_N*THREADS) == 8 exactly
#define TOTAL_BLOCKS (NB * BLOCKS_PER_N)

// Global scratch (zero-initialized at module load; kernel restores to zero
// after every run so graph replays are deterministic).
__device__ float        g_num[NB * NC];
__device__ float        g_den[NB * NC];
__device__ unsigned int g_done;

__global__ __launch_bounds__(THREADS) void dice_fused_kernel(
    const float* __restrict__ predict,
    const int*   __restrict__ target,
    const int*   __restrict__ masks,
    float*       __restrict__ out)
{
    const int n     = blockIdx.x / BLOCKS_PER_N;
    const int chunk = blockIdx.x % BLOCKS_PER_N;

    const float4* __restrict__ p  = (const float4*)(predict + (size_t)n * NC * MPIX);
    const int4*   __restrict__ tg = (const int4*)(target + (size_t)n * MPIX);
    const int4*   __restrict__ mk = (const int4*)(masks  + (size_t)n * MPIX);

    float num0 = 0.f, num1 = 0.f, num2 = 0.f, num3 = 0.f;
    float den0 = 0.f, den1 = 0.f, den2 = 0.f, den3 = 0.f;

    const int base   = chunk * THREADS + threadIdx.x;
    const int stride = BLOCKS_PER_N * THREADS;

    #pragma unroll
    for (int it = 0; it < ITERS; it++) {
        const int i = base + it * stride;
        // 6 independent 128B loads per iter -> high MLP
        float4 a = p[i];            // class 0, pixels 4i..4i+3
        float4 b = p[i + MV];       // class 1
        float4 c = p[i + 2 * MV];   // class 2
        float4 d = p[i + 3 * MV];   // class 3
        int4   t = tg[i];
        int4   m = mk[i];

        const float xa[4] = {a.x, a.y, a.z, a.w};
        const float xb[4] = {b.x, b.y, b.z, b.w};
        const float xc[4] = {c.x, c.y, c.z, c.w};
        const float xd[4] = {d.x, d.y, d.z, d.w};
        const int   tt[4] = {t.x, t.y, t.z, t.w};
        const int   mm[4] = {m.x, m.y, m.z, m.w};

        #pragma unroll
        for (int j = 0; j < 4; j++) {
            const float v0 = xa[j], v1 = xb[j], v2 = xc[j], v3 = xd[j];
            const int   tj = tt[j];
            const bool  on = (mm[j] >= 1);

            // 4-way softmax (inputs ~N(0,1): max-subtract for safety, cheap FMA work)
            float mx = fmaxf(fmaxf(v0, v1), fmaxf(v2, v3));
            float e0 = __expf(v0 - mx);
            float e1 = __expf(v1 - mx);
            float e2 = __expf(v2 - mx);
            float e3 = __expf(v3 - mx);
            float inv = __fdividef(1.0f, e0 + e1 + e2 + e3);

            // one-hot selects (branch-free)
            float h0 = (tj == 0) ? 1.0f : 0.0f;
            float h1 = (tj == 1) ? 1.0f : 0.0f;
            float h2 = (tj == 2) ? 1.0f : 0.0f;
            float h3 = (tj == 3) ? 1.0f : 0.0f;

            // p_eff = mask ? softmax : onehot
            float p0v = on ? e0 * inv : h0;
            float p1v = on ? e1 * inv : h1;
            float p2v = on ? e2 * inv : h2;
            float p3v = on ? e3 * inv : h3;

            // num_c += onehot_c * p_c ; den_c += p_c^2 + onehot_c
            num0 += h0 * p0v;  den0 += p0v * p0v + h0;
            num1 += h1 * p1v;  den1 += p1v * p1v + h1;
            num2 += h2 * p2v;  den2 += p2v * p2v + h2;
            num3 += h3 * p3v;  den3 += p3v * p3v + h3;
        }
    }

    // ---- warp-level reduction (8 values) ----
    #pragma unroll
    for (int off = 16; off > 0; off >>= 1) {
        num0 += __shfl_xor_sync(0xffffffffu, num0, off);
        num1 += __shfl_xor_sync(0xffffffffu, num1, off);
        num2 += __shfl_xor_sync(0xffffffffu, num2, off);
        num3 += __shfl_xor_sync(0xffffffffu, num3, off);
        den0 += __shfl_xor_sync(0xffffffffu, den0, off);
        den1 += __shfl_xor_sync(0xffffffffu, den1, off);
        den2 += __shfl_xor_sync(0xffffffffu, den2, off);
        den3 += __shfl_xor_sync(0xffffffffu, den3, off);
    }

    __shared__ float s_acc[8];
    if (threadIdx.x < 8) s_acc[threadIdx.x] = 0.0f;
    __syncthreads();

    if ((threadIdx.x & 31) == 0) {
        atomicAdd(&s_acc[0], num0);
        atomicAdd(&s_acc[1], num1);
        atomicAdd(&s_acc[2], num2);
        atomicAdd(&s_acc[3], num3);
        atomicAdd(&s_acc[4], den0);
        atomicAdd(&s_acc[5], den1);
        atomicAdd(&s_acc[6], den2);
        atomicAdd(&s_acc[7], den3);
    }
    __syncthreads();

    if (threadIdx.x < 4) {
        atomicAdd(&g_num[n * NC + threadIdx.x], s_acc[threadIdx.x]);
        atomicAdd(&g_den[n * NC + threadIdx.x], s_acc[4 + threadIdx.x]);
    }

    // ---- last-block-done finalize ----
    __shared__ bool s_last;
    __threadfence();                       // publish our g_num/g_den adds
    if (threadIdx.x == 0) {
        unsigned int prev = atomicInc(&g_done, TOTAL_BLOCKS - 1);
        s_last = (prev == TOTAL_BLOCKS - 1);
    }
    __syncthreads();

    if (s_last) {
        __shared__ float s_loss[64];
        const int i = threadIdx.x;
        if (i < 64) {
            // g_done wrap already reset the counter; read totals (fenced above)
            float v = 1.0f - (g_num[i] + 1.0f) / (g_den[i] + 1.0f);
            s_loss[i] = v;
        }
        __syncthreads();
        if (i < 32) {
            float x = s_loss[i] + s_loss[i + 32];
            #pragma unroll
            for (int off = 16; off > 0; off >>= 1)
                x += __shfl_xor_sync(0xffffffffu, x, off);
            if (i == 0) out[0] = x * (1.0f / (NB * NC));
        }
        __syncthreads();
        // Reset accumulators so the next graph replay starts from zero.
        // (atomicInc with bound TOTAL_BLOCKS-1 wrapped g_done back to 0.)
        if (i < 64) {
            g_num[i] = 0.0f;
            g_den[i] = 0.0f;
        }
    }
}

extern "C" void kernel_launch(void* const* d_in, const int* in_sizes, int n_in,
                              void* d_out, int out_size) {
    const float* predict = (const float*)d_in[0];
    const int*   target  = (const int*)d_in[1];
    const int*   masks   = (const int*)d_in[2];
    float*       out     = (float*)d_out;

    dice_fused_kernel<<<TOTAL_BLOCKS, THREADS>>>(predict, target, masks, out);
}